// round 13
// baseline (speedup 1.0000x reference)
#include <cuda_runtime.h>
#include <cstdint>

// DropBlock fused single kernel, high-occupancy variant.
//   x: (32,256,56,56) fp32, u: (56,56) fp32
//   seed = (u < GAMMA); dilated = backward 7x7 window max (separable);
//   bm = 1 - dilated; scale = 3136/sum(bm); out = x * bm * scale.

#define H 56
#define W 56
#define HW 3136
#define HW4 784          // HW/4
#define W4 14            // W/4
#define NT 256
#define NCTA 1176        // 49*24 -> NCTA*NT = 301056 = 784*384 (phase-aligned)

__device__ __forceinline__ float4 fmax4(float4 a, float4 b) {
    return make_float4(fmaxf(a.x,b.x), fmaxf(a.y,b.y), fmaxf(a.z,b.z), fmaxf(a.w,b.w));
}

__global__ void __launch_bounds__(NT, 8)
dropblock_fused_kernel(const float4* __restrict__ x, const float* __restrict__ u,
                       float4* __restrict__ out, int n4) {
    __shared__ float sa[HW];      // seed, later bm
    __shared__ float sb[HW];      // row-max
    __shared__ float sred[8];
    __shared__ float sscale;

    const int t = threadIdx.x;
    const float GAMMA = (float)(0.1 * (3136.0 / (49.0 * 2500.0)));

    // --- seed mask ---
    for (int i = t; i < HW; i += NT)
        sa[i] = (u[i] < GAMMA) ? 1.0f : 0.0f;
    __syncthreads();

    // --- row-wise backward 7-max (vectorized: 4 outputs per float4 unit) ---
    for (int uq = t; uq < HW4; uq += NT) {
        int w4 = uq % W4;
        const float4* row = ((const float4*)sa) + (uq - w4);
        float4 Z = make_float4(0.f, 0.f, 0.f, 0.f);
        float4 A = (w4 >= 2) ? row[w4 - 2] : Z;   // zeros emulate edge clamp
        float4 B = (w4 >= 1) ? row[w4 - 1] : Z;
        float4 C = row[w4];
        float v[12] = {A.x,A.y,A.z,A.w, B.x,B.y,B.z,B.w, C.x,C.y,C.z,C.w};
        float o[4];
        #pragma unroll
        for (int j = 0; j < 4; j++) {
            float m = v[j + 2];
            #pragma unroll
            for (int k = j + 3; k <= j + 8; k++) m = fmaxf(m, v[k]);
            o[j] = m;
        }
        ((float4*)sb)[uq] = make_float4(o[0], o[1], o[2], o[3]);
    }
    __syncthreads();

    // --- column-wise backward 7-max, bm = 1 - dilated, local sum ---
    float lsum = 0.0f;
    for (int uq = t; uq < HW4; uq += NT) {
        int w4 = uq % W4;
        int h  = uq / W4;
        float4 mx = ((const float4*)sb)[uq];
        int h0 = h - 6; if (h0 < 0) h0 = 0;
        for (int hh = h0; hh < h; hh++)
            mx = fmax4(mx, ((const float4*)sb)[hh * W4 + w4]);
        float4 bm = make_float4(1.f-mx.x, 1.f-mx.y, 1.f-mx.z, 1.f-mx.w);
        lsum += bm.x + bm.y + bm.z + bm.w;
        ((float4*)sa)[uq] = bm;     // seed no longer needed
    }

    // --- block reduce (exact: bm entries are 0/1) ---
    #pragma unroll
    for (int off = 16; off > 0; off >>= 1)
        lsum += __shfl_xor_sync(0xFFFFFFFF, lsum, off);
    if ((t & 31) == 0) sred[t >> 5] = lsum;
    __syncthreads();
    if (t == 0) {
        float s = 0.f;
        #pragma unroll
        for (int k = 0; k < 8; k++) s += sred[k];
        sscale = (float)HW / s;
    }
    __syncthreads();

    // --- per-thread loop-invariant mask value (phase-aligned grid) ---
    const int gt   = blockIdx.x * NT + t;
    const int step = NCTA * NT;              // 301056 = 784*384
    const float scale = sscale;
    float4 m = ((const float4*)sa)[gt % HW4];
    m.x *= scale; m.y *= scale; m.z *= scale; m.w *= scale;

    // --- streaming multiply, MLP=4 ---
    int i = gt;
    const int limit4 = n4 - 3 * step;
    for (; i < limit4; i += 4 * step) {
        float4 a = __ldg(&x[i]);
        float4 b = __ldg(&x[i +     step]);
        float4 c = __ldg(&x[i + 2 * step]);
        float4 d = __ldg(&x[i + 3 * step]);
        a.x*=m.x; a.y*=m.y; a.z*=m.z; a.w*=m.w;
        b.x*=m.x; b.y*=m.y; b.z*=m.z; b.w*=m.w;
        c.x*=m.x; c.y*=m.y; c.z*=m.z; c.w*=m.w;
        d.x*=m.x; d.y*=m.y; d.z*=m.z; d.w*=m.w;
        __stcs(&out[i],            a);
        __stcs(&out[i +     step], b);
        __stcs(&out[i + 2 * step], c);
        __stcs(&out[i + 3 * step], d);
    }
    for (; i < n4; i += step) {
        float4 a = __ldg(&x[i]);
        a.x*=m.x; a.y*=m.y; a.z*=m.z; a.w*=m.w;
        __stcs(&out[i], a);
    }
}

extern "C" void kernel_launch(void* const* d_in, const int* in_sizes, int n_in,
                              void* d_out, int out_size) {
    const float* x = (const float*)d_in[0];
    const float* u = (const float*)d_in[1];
    float* out = (float*)d_out;

    // Ensure the SM smem carveout allows 8 resident CTAs (8 x ~25KB).
    // Host-side attribute set: idempotent, no allocation, capture-safe.
    cudaFuncSetAttribute(dropblock_fused_kernel,
                         cudaFuncAttributePreferredSharedMemoryCarveout, 100);

    const int n4 = out_size / 4;   // 6,422,528
    dropblock_fused_kernel<<<NCTA, NT>>>((const float4*)x, u, (float4*)out, n4);
}

// round 14
// speedup vs baseline: 1.2072x; 1.2072x over previous
#include <cuda_runtime.h>
#include <cstdint>

// DropBlock, two kernels:
//   K1 (1 CTA): seed=(u<GAMMA); separable backward 7x7 max; bm=1-dilated;
//               scale=3136/sum(bm); writes ms[i]=bm[i]*scale LUT to global.
//   K2: out = x * ms[i % 3136], phase-aligned grid, MLP=8 streaming.

#define H 56
#define W 56
#define HW 3136
#define HW4 784          // HW/4
#define W4 14            // W/4

__device__ float4 d_ms4[HW4];    // mask*scale LUT

__device__ __forceinline__ float4 fmax4(float4 a, float4 b) {
    return make_float4(fmaxf(a.x,b.x), fmaxf(a.y,b.y), fmaxf(a.z,b.z), fmaxf(a.w,b.w));
}

// ---------------------------------------------------------------------------
// Kernel 1: separable mask computation, single CTA of 1024 threads.
// ---------------------------------------------------------------------------
__global__ void __launch_bounds__(1024, 1)
dropblock_mask_kernel(const float* __restrict__ u) {
    __shared__ float sa[HW];     // seed
    __shared__ float sb[HW];     // row-max
    __shared__ float sred[32];
    __shared__ float sscale;

    const int t = threadIdx.x;
    const float GAMMA = (float)(0.1 * (3136.0 / (49.0 * 2500.0)));

    // seed
    for (int i = t; i < HW; i += 1024)
        sa[i] = (u[i] < GAMMA) ? 1.0f : 0.0f;
    __syncthreads();

    // row-wise backward 7-max (one float4 unit per thread; 784 < 1024)
    if (t < HW4) {
        int w4 = t % W4;
        const float4* row = ((const float4*)sa) + (t - w4);
        float4 Z = make_float4(0.f, 0.f, 0.f, 0.f);
        float4 A = (w4 >= 2) ? row[w4 - 2] : Z;   // zeros emulate edge clamp
        float4 B = (w4 >= 1) ? row[w4 - 1] : Z;
        float4 C = row[w4];
        float v[12] = {A.x,A.y,A.z,A.w, B.x,B.y,B.z,B.w, C.x,C.y,C.z,C.w};
        float o[4];
        #pragma unroll
        for (int j = 0; j < 4; j++) {
            float m = v[j + 2];
            #pragma unroll
            for (int k = j + 3; k <= j + 8; k++) m = fmaxf(m, v[k]);
            o[j] = m;
        }
        ((float4*)sb)[t] = make_float4(o[0], o[1], o[2], o[3]);
    }
    __syncthreads();

    // column-wise backward 7-max, bm = 1 - dilated, per-thread partial sum
    float lsum = 0.0f;
    float4 bmv;
    if (t < HW4) {
        int w4 = t % W4;
        int h  = t / W4;
        float4 mx = ((const float4*)sb)[t];
        int h0 = h - 6; if (h0 < 0) h0 = 0;
        for (int hh = h0; hh < h; hh++)
            mx = fmax4(mx, ((const float4*)sb)[hh * W4 + w4]);
        bmv = make_float4(1.f-mx.x, 1.f-mx.y, 1.f-mx.z, 1.f-mx.w);
        lsum = bmv.x + bmv.y + bmv.z + bmv.w;
    }

    // block reduce (exact: bm entries are 0/1)
    #pragma unroll
    for (int off = 16; off > 0; off >>= 1)
        lsum += __shfl_xor_sync(0xFFFFFFFF, lsum, off);
    if ((t & 31) == 0) sred[t >> 5] = lsum;
    __syncthreads();
    if (t == 0) {
        float s = 0.f;
        #pragma unroll
        for (int k = 0; k < 32; k++) s += sred[k];
        sscale = (float)HW / s;
    }
    __syncthreads();

    if (t < HW4) {
        float sc = sscale;
        d_ms4[t] = make_float4(bmv.x*sc, bmv.y*sc, bmv.z*sc, bmv.w*sc);
    }
}

// ---------------------------------------------------------------------------
// Kernel 2: streaming multiply. Grid: 3136 CTAs x 256 thr = 802816 threads
//   = 784*1024 (phase-aligned -> per-thread mask is loop-invariant).
//   n4 = 6,422,528 = 802816 * 8 -> exactly 8 float4 per thread, no tail.
//   All 8 loads front-batched (MLP=8), then 8 streaming stores.
// ---------------------------------------------------------------------------
#define ANT 256
#define ANCTA 3136
#define ASTEP (ANCTA * ANT)      // 802816

__global__ void __launch_bounds__(ANT)
dropblock_apply_kernel(const float4* __restrict__ x, float4* __restrict__ out) {
    const int gt = blockIdx.x * ANT + threadIdx.x;

    float4 m = d_ms4[gt % HW4];      // loop-invariant (ASTEP % 784 == 0)

    float4 v[8];
    #pragma unroll
    for (int k = 0; k < 8; k++)
        v[k] = __ldg(&x[gt + k * ASTEP]);

    #pragma unroll
    for (int k = 0; k < 8; k++) {
        v[k].x *= m.x; v[k].y *= m.y; v[k].z *= m.z; v[k].w *= m.w;
        __stcs(&out[gt + k * ASTEP], v[k]);
    }
}

// ---------------------------------------------------------------------------
extern "C" void kernel_launch(void* const* d_in, const int* in_sizes, int n_in,
                              void* d_out, int out_size) {
    const float* x = (const float*)d_in[0];
    const float* u = (const float*)d_in[1];
    float* out = (float*)d_out;

    dropblock_mask_kernel<<<1, 1024>>>(u);
    dropblock_apply_kernel<<<ANCTA, ANT>>>((const float4*)x, (float4*)out);
}